// round 9
// baseline (speedup 1.0000x reference)
#include <cuda_runtime.h>
#include <cstdint>

// Problem constants
#define BATCH 2
#define A_    2
#define C_    10
#define HW_   1024
#define NBOX  2048
#define TILE  128
#define LOG2E 1.4426950408889634f
#define PI_F  3.14159265358979323846f

// Output layout: out_scores [0,40960) | bbox [40960,69632) | pp [69632,131072)
#define OUT_BBOX 40960
#define OUT_PP   69632

// ---------------- scratch tables (SoA-group layouts) ----------------
// g_bev4: [b][2][HW] float4
//   g0 = (x1a0, x1a1, y1a0, y1a1)   g1 = (x2a0, x2a1, y2a0, y2a1)
__device__ __align__(16) float4 g_bev4[BATCH * 2 * HW_];
// g_pc4: [b][8][HW] float4
//   g=0..4 : (w[2k,a0], w[2k+1,a0], w[2k,a1], w[2k+1,a1])   (w = exp(score))
//   g=5    : (p1[0..3])   g=6 : (p1[4..7])   g=7 : (p1[8],p1[9],area0,area1)
__device__ __align__(16) float4 g_pc4[BATCH * 8 * HW_];
// g_p0: [b*HW][10]  (p0[c] * log2e)
__device__ __align__(8)  float  g_p0[BATCH * HW_ * 10];
__device__ float g_scinv[BATCH * C_];

typedef unsigned long long ull;
// partial sums: [h][cell][k][{acc0,acc1,sm0,sm1}]
__device__ __align__(16) ull g_part[2 * NBOX * 5 * 4];

// ---------------- helpers ----------------
__device__ __forceinline__ float ex2(float x) {
    float y; asm("ex2.approx.f32 %0, %1;" : "=f"(y) : "f"(x)); return y;
}
__device__ __forceinline__ float rcpf(float x) {
    float y; asm("rcp.approx.f32 %0, %1;" : "=f"(y) : "f"(x)); return y;
}
__device__ __forceinline__ ull pk(float a, float b) {
    ull r; asm("mov.b64 %0, {%1,%2};" : "=l"(r) : "f"(a), "f"(b)); return r;
}
__device__ __forceinline__ void upk(ull v, float& a, float& b) {
    asm("mov.b64 {%0,%1}, %2;" : "=f"(a), "=f"(b) : "l"(v));
}
__device__ __forceinline__ ull mul2(ull a, ull b) {
    ull r; asm("mul.rn.f32x2 %0, %1, %2;" : "=l"(r) : "l"(a), "l"(b)); return r;
}
__device__ __forceinline__ ull fma2(ull a, ull b, ull c) {
    ull r; asm("fma.rn.f32x2 %0, %1, %2, %3;" : "=l"(r) : "l"(a), "l"(b), "l"(c)); return r;
}
__device__ __forceinline__ ull add2(ull a, ull b) {
    ull r; asm("add.rn.f32x2 %0, %1, %2;" : "=l"(r) : "l"(a), "l"(b)); return r;
}
__device__ __forceinline__ void cpasync16(uint32_t saddr, const void* g) {
    asm volatile("cp.async.cg.shared.global [%0], [%1], 16;" :: "r"(saddr), "l"(g));
}

// ---------------------------------------------------------------------------
// K1 fused: prep tables (blocks 0..7) + score softmax denominators (8..27)
// ---------------------------------------------------------------------------
__global__ void k_fused(const float* __restrict__ scores,
                        const float* __restrict__ pp,
                        const float* __restrict__ dec) {
    int blk = blockIdx.x;
    int tid = threadIdx.x;

    if (blk < 8) {
        int idx = blk * 256 + tid;
        int b = idx >> 10;
        int hw = idx & (HW_ - 1);

        float x1a[2], y1a[2], x2a[2], y2a[2], area[2];
#pragma unroll
        for (int a = 0; a < 2; a++) {
            const float* d7 = dec + ((size_t)b * NBOX + hw * 2 + a) * 7;
            float x = d7[0], y = d7[1], dx = d7[3], dy = d7[4], yaw = d7[6];
            float normed = fabsf(yaw - floorf(yaw / PI_F + 0.5f) * PI_F);
            bool sw = normed > 0.25f * PI_F;
            float w = sw ? dy : dx;
            float h = sw ? dx : dy;
            x1a[a] = x - 0.5f * w; y1a[a] = y - 0.5f * h;
            x2a[a] = x + 0.5f * w; y2a[a] = y + 0.5f * h;
            area[a] = (x2a[a] - x1a[a]) * (y2a[a] - y1a[a]);
        }
        float4* bv = g_bev4 + (size_t)b * 2 * HW_ + hw;
        bv[0]    = make_float4(x1a[0], x1a[1], y1a[0], y1a[1]);
        bv[HW_]  = make_float4(x2a[0], x2a[1], y2a[0], y2a[1]);

        float e[C_][2], p1[C_];
#pragma unroll
        for (int c = 0; c < C_; c++) {
            e[c][0] = __expf(scores[((b * A_ + 0) * C_ + c) * HW_ + hw]);
            e[c][1] = __expf(scores[((b * A_ + 1) * C_ + c) * HW_ + hw]);
            p1[c]   = pp[((size_t)b * 30 + c * 3 + 1) * HW_ + hw];
            g_p0[(size_t)idx * 10 + c] =
                pp[((size_t)b * 30 + c * 3) * HW_ + hw] * LOG2E;
        }
        float4* pc = g_pc4 + (size_t)b * 8 * HW_ + hw;
#pragma unroll
        for (int k = 0; k < 5; k++)
            pc[k * HW_] = make_float4(e[2 * k][0], e[2 * k + 1][0],
                                      e[2 * k][1], e[2 * k + 1][1]);
        pc[5 * HW_] = make_float4(p1[0], p1[1], p1[2], p1[3]);
        pc[6 * HW_] = make_float4(p1[4], p1[5], p1[6], p1[7]);
        pc[7 * HW_] = make_float4(p1[8], p1[9], area[0], area[1]);
    } else {
        int s = blk - 8;
        int b = s / C_, c = s % C_;
        __shared__ float red[256];
        float acc = 0.f;
        for (int m = tid; m < NBOX; m += 256) {
            int a = m & 1, hw = m >> 1;
            acc += __expf(scores[((b * A_ + a) * C_ + c) * HW_ + hw]);
        }
        red[tid] = acc;
        __syncthreads();
#pragma unroll
        for (int o = 128; o > 0; o >>= 1) {
            if (tid < o) red[tid] += red[tid + o];
            __syncthreads();
        }
        if (tid == 0) g_scinv[b * C_ + c] = 1.0f / red[0];
    }
}

// ---------------------------------------------------------------------------
// K2 main: blocks [0,1024): block q -> n-quad q>>1, m-half q&1 (512 m-cells,
//          4 tiles). One warp per n-cell. Partials to g_part.
//          Blocks >= 1024: bbox/pp pass-through copies (overlapped).
// ---------------------------------------------------------------------------
__device__ __forceinline__ float iou1(float ax1, float ay1, float ax2, float ay2, float aa,
                                      float bx1, float by1, float bx2, float by2, float ba) {
    float ltx = fmaxf(ax1, bx1);
    float lty = fmaxf(ay1, by1);
    float rbx = fminf(ax2, bx2);
    float rby = fminf(ay2, by2);
    float w = fmaxf(rbx - ltx, 0.f);
    float h = fmaxf(rby - lty, 0.f);
    float inter = w * h;
    float uni = fmaxf(aa + ba - inter, 1e-6f);
    return inter * LOG2E * rcpf(uni);
}

__global__ void __launch_bounds__(128, 5) k_main(
        const float* __restrict__ bbox, const float* __restrict__ pp,
        float* __restrict__ out) {
    if (blockIdx.x >= 1024) {
        // pass-through copies: 88 blocks * 256 float4 = 22528 f4
        int base = (blockIdx.x - 1024) * 256 + threadIdx.x;
#pragma unroll
        for (int r = 0; r < 2; r++) {
            int i = base + r * 128;
            if (i < 7168)
                ((float4*)(out + OUT_BBOX))[i] = ((const float4*)bbox)[i];
            else
                ((float4*)(out + OUT_PP))[i - 7168] = ((const float4*)pp)[i - 7168];
        }
        return;
    }

    __shared__ __align__(16) float4     sb[2][2 * TILE];  // bev groups
    __shared__ __align__(16) ulonglong2 sp[2][8 * TILE];  // pc groups

    int tid = threadIdx.x;
    int lane = tid & 31;
    int h = blockIdx.x & 1;                      // m-half
    int gw = (blockIdx.x >> 1) * 4 + (tid >> 5); // n-cell index [0,2048)
    int b = gw >> 10;
    int hwn = gw & (HW_ - 1);

    // n-side invariants
    float4 ng0 = g_bev4[(size_t)b * 2 * HW_ + hwn];
    float4 ng1 = g_bev4[(size_t)b * 2 * HW_ + HW_ + hwn];
    float4 ng7 = g_pc4[(size_t)b * 8 * HW_ + 7 * HW_ + hwn];
    float n0x1 = ng0.x, n1x1 = ng0.y, n0y1 = ng0.z, n1y1 = ng0.w;
    float n0x2 = ng1.x, n1x2 = ng1.y, n0y2 = ng1.z, n1y2 = ng1.w;
    float an0 = ng7.z, an1 = ng7.w;

    ull p0p[5];
#pragma unroll
    for (int k = 0; k < 5; k++) {
        float2 t = *(const float2*)(g_p0 + (size_t)gw * 10 + 2 * k);
        p0p[k] = pk(t.x, t.y);
    }

    ull acc0p[5], acc1p[5], sm0p[5], sm1p[5];
#pragma unroll
    for (int k = 0; k < 5; k++) { acc0p[k] = 0; acc1p[k] = 0; sm0p[k] = 0; sm1p[k] = 0; }

    const float4* gb = g_bev4 + (size_t)b * 2 * HW_ + h * 512;
    const float4* gp = g_pc4 + (size_t)b * 8 * HW_ + h * 512;

    // prefetch tile 0
    {
        uint32_t sba = (uint32_t)__cvta_generic_to_shared(&sb[0][0]);
        uint32_t spa = (uint32_t)__cvta_generic_to_shared(&sp[0][0]);
#pragma unroll
        for (int g = 0; g < 2; g++)
            cpasync16(sba + (g * TILE + tid) * 16, gb + g * HW_ + tid);
#pragma unroll
        for (int g = 0; g < 8; g++)
            cpasync16(spa + (g * TILE + tid) * 16, gp + g * HW_ + tid);
        asm volatile("cp.async.commit_group;");
    }

    for (int t = 0; t < 4; t++) {
        if (t < 3) {
            int nb = (t + 1) & 1;
            uint32_t sba = (uint32_t)__cvta_generic_to_shared(&sb[nb][0]);
            uint32_t spa = (uint32_t)__cvta_generic_to_shared(&sp[nb][0]);
            int off = (t + 1) * TILE + tid;
#pragma unroll
            for (int g = 0; g < 2; g++)
                cpasync16(sba + (g * TILE + tid) * 16, gb + g * HW_ + off);
#pragma unroll
            for (int g = 0; g < 8; g++)
                cpasync16(spa + (g * TILE + tid) * 16, gp + g * HW_ + off);
            asm volatile("cp.async.commit_group;");
            asm volatile("cp.async.wait_group 1;");
        } else {
            asm volatile("cp.async.wait_group 0;");
        }
        __syncthreads();

        const float4*     SB = sb[t & 1];
        const ulonglong2* SP = sp[t & 1];
#pragma unroll 2
        for (int j = 0; j < 4; j++) {
            int m = lane + j * 32;
            float4 bg0 = SB[m];            // (x1a0,x1a1,y1a0,y1a1)
            float4 bg1 = SB[TILE + m];     // (x2a0,x2a1,y2a0,y2a1)
            float4 G7f = ((const float4*)SP)[7 * TILE + m]; // p1[8],p1[9],area0,area1

            float q00 = iou1(n0x1, n0y1, n0x2, n0y2, an0, bg0.x, bg0.z, bg1.x, bg1.z, G7f.z);
            float q01 = iou1(n0x1, n0y1, n0x2, n0y2, an0, bg0.y, bg0.w, bg1.y, bg1.w, G7f.w);
            float q10 = iou1(n1x1, n1y1, n1x2, n1y2, an1, bg0.x, bg0.z, bg1.x, bg1.z, G7f.z);
            float q11 = iou1(n1x1, n1y1, n1x2, n1y2, an1, bg0.y, bg0.w, bg1.y, bg1.w, G7f.w);

            float e00 = ex2(q00), e01 = ex2(q01);
            float e10 = ex2(q10), e11 = ex2(q11);
            ull e00s = pk(e00, e00), e01s = pk(e01, e01);
            ull e10s = pk(e10, e10), e11s = pk(e11, e11);
            ull es0s = pk(e00 + e01, e00 + e01);
            ull es1s = pk(e10 + e11, e10 + e11);

            ulonglong2 G5 = SP[5 * TILE + m];
            ulonglong2 G6 = SP[6 * TILE + m];
            ull p1p[5] = { G5.x, G5.y, G6.x, G6.y, pk(G7f.x, G7f.y) };

#pragma unroll
            for (int k = 0; k < 5; k++) {
                ull tt = mul2(p0p[k], p1p[k]);
                float b0, b1; upk(tt, b0, b1);
                ull ebp = pk(ex2(b0), ex2(b1));        // exp(bias) c-pair

                ulonglong2 Wk = SP[k * TILE + m];      // w0p = a0 pair, w1p = a1 pair
                ull s0p = fma2(e01s, Wk.y, mul2(e00s, Wk.x));
                ull s1p = fma2(e11s, Wk.y, mul2(e10s, Wk.x));
                acc0p[k] = fma2(ebp, s0p, acc0p[k]);
                acc1p[k] = fma2(ebp, s1p, acc1p[k]);
                sm0p[k]  = fma2(ebp, es0s, sm0p[k]);
                sm1p[k]  = fma2(ebp, es1s, sm1p[k]);
            }
        }
        __syncthreads();
    }

    // warp butterfly reduction
#pragma unroll
    for (int o = 16; o > 0; o >>= 1) {
#pragma unroll
        for (int k = 0; k < 5; k++) {
            acc0p[k] = add2(acc0p[k], __shfl_xor_sync(0xffffffffu, acc0p[k], o));
            acc1p[k] = add2(acc1p[k], __shfl_xor_sync(0xffffffffu, acc1p[k], o));
            sm0p[k]  = add2(sm0p[k],  __shfl_xor_sync(0xffffffffu, sm0p[k],  o));
            sm1p[k]  = add2(sm1p[k],  __shfl_xor_sync(0xffffffffu, sm1p[k],  o));
        }
    }

    if (lane == 0) {
        ull* P = g_part + ((size_t)(h * NBOX + gw) * 5) * 4;
#pragma unroll
        for (int k = 0; k < 5; k++) {
            P[k * 4 + 0] = acc0p[k];
            P[k * 4 + 1] = acc1p[k];
            P[k * 4 + 2] = sm0p[k];
            P[k * 4 + 3] = sm1p[k];
        }
    }
}

// ---------------------------------------------------------------------------
// K3 combine: add m-half partials, divide, scale, store. 2048*5 threads.
// ---------------------------------------------------------------------------
__global__ void k_comb(float* __restrict__ out) {
    int i = blockIdx.x * 256 + threadIdx.x;   // [0, 10240)
    int cell = i / 5;
    int k = i - cell * 5;
    int b = cell >> 10;
    int hwn = cell & (HW_ - 1);

    const ull* P0 = g_part + ((size_t)cell * 5 + k) * 4;
    const ull* P1 = P0 + (size_t)NBOX * 5 * 4;
    ull a0 = add2(P0[0], P1[0]);
    ull a1 = add2(P0[1], P1[1]);
    ull s0 = add2(P0[2], P1[2]);
    ull s1 = add2(P0[3], P1[3]);

    int c0 = 2 * k, c1 = 2 * k + 1;
    float i0 = g_scinv[b * C_ + c0];
    float i1 = g_scinv[b * C_ + c1];
    float v0, v1, d0, d1;
    upk(a0, v0, v1); upk(s0, d0, d1);
    out[((b * A_ + 0) * C_ + c0) * HW_ + hwn] = v0 * rcpf(d0) * i0;
    out[((b * A_ + 0) * C_ + c1) * HW_ + hwn] = v1 * rcpf(d1) * i1;
    upk(a1, v0, v1); upk(s1, d0, d1);
    out[((b * A_ + 1) * C_ + c0) * HW_ + hwn] = v0 * rcpf(d0) * i0;
    out[((b * A_ + 1) * C_ + c1) * HW_ + hwn] = v1 * rcpf(d1) * i1;
}

extern "C" void kernel_launch(void* const* d_in, const int* in_sizes, int n_in,
                              void* d_out, int out_size) {
    const float* scores = (const float*)d_in[0];
    const float* bbox = (const float*)d_in[1];
    const float* pp = (const float*)d_in[2];
    const float* dec = (const float*)d_in[3];
    float* out = (float*)d_out;

    k_fused<<<28, 256>>>(scores, pp, dec);
    k_main<<<1024 + 88, 128>>>(bbox, pp, out);
    k_comb<<<40, 256>>>(out);
}

// round 10
// speedup vs baseline: 1.0044x; 1.0044x over previous
#include <cuda_runtime.h>
#include <cstdint>

// Problem constants
#define BATCH 2
#define A_    2
#define C_    10
#define HW_   1024
#define NBOX  2048
#define TILE  128
#define LOG2E 1.4426950408889634f
#define PI_F  3.14159265358979323846f

// Output layout: out_scores [0,40960) | bbox [40960,69632) | pp [69632,131072)
#define OUT_BBOX 40960
#define OUT_PP   69632

// ---------------- scratch tables (SoA-group layouts) ----------------
// g_bev4: [b][2][HW] float4
//   g0 = (x1a0, x1a1, y1a0, y1a1)   g1 = (x2a0, x2a1, y2a0, y2a1)
__device__ __align__(16) float4 g_bev4[BATCH * 2 * HW_];
// g_pc4: [b][8][HW] float4
//   g=0..4 : (w[2k,a0], w[2k+1,a0], w[2k,a1], w[2k+1,a1])   (w = exp(score))
//   g=5    : (p1[0..3])   g=6 : (p1[4..7])   g=7 : (p1[8],p1[9],area0,area1)
__device__ __align__(16) float4 g_pc4[BATCH * 8 * HW_];
// g_p0f2: [b][k][hw] float2   (p0[2k],p0[2k+1]) * log2e
__device__ __align__(8)  float2 g_p0f2[BATCH * 5 * HW_];
__device__ float g_scinv[BATCH * C_];

typedef unsigned long long ull;
// partial sums: [h][cell][k][{acc0,acc1,sm0,sm1}]
__device__ __align__(16) ull g_part[2 * NBOX * 5 * 4];

// ---------------- helpers ----------------
__device__ __forceinline__ float ex2(float x) {
    float y; asm("ex2.approx.f32 %0, %1;" : "=f"(y) : "f"(x)); return y;
}
__device__ __forceinline__ float rcpf(float x) {
    float y; asm("rcp.approx.f32 %0, %1;" : "=f"(y) : "f"(x)); return y;
}
__device__ __forceinline__ ull pk(float a, float b) {
    ull r; asm("mov.b64 %0, {%1,%2};" : "=l"(r) : "f"(a), "f"(b)); return r;
}
__device__ __forceinline__ void upk(ull v, float& a, float& b) {
    asm("mov.b64 {%0,%1}, %2;" : "=f"(a), "=f"(b) : "l"(v));
}
__device__ __forceinline__ ull mul2(ull a, ull b) {
    ull r; asm("mul.rn.f32x2 %0, %1, %2;" : "=l"(r) : "l"(a), "l"(b)); return r;
}
__device__ __forceinline__ ull fma2(ull a, ull b, ull c) {
    ull r; asm("fma.rn.f32x2 %0, %1, %2, %3;" : "=l"(r) : "l"(a), "l"(b), "l"(c)); return r;
}
__device__ __forceinline__ ull add2(ull a, ull b) {
    ull r; asm("add.rn.f32x2 %0, %1, %2;" : "=l"(r) : "l"(a), "l"(b)); return r;
}
__device__ __forceinline__ void cpasync16(uint32_t saddr, const void* g) {
    asm volatile("cp.async.cg.shared.global [%0], [%1], 16;" :: "r"(saddr), "l"(g));
}

// ---------------------------------------------------------------------------
// K1 fused prep: wide, coalesced, elementwise slices.
//   [0,40)    wpack : exp(scores) -> g_pc4 groups 0..4
//   [40,56)   p1pack: pp -> g_pc4 groups 5,6
//   [56,64)   p1tail: pp -> g_pc4 group 7 .xy
//   [64,104)  p0pack: pp*log2e -> g_p0f2
//   [104,112) bev   : dec -> g_bev4 + areas -> g_pc4 group 7 .zw
//   [112,132) scsum : softmax denominators
// ---------------------------------------------------------------------------
__global__ void k_fused(const float* __restrict__ scores,
                        const float* __restrict__ pp,
                        const float* __restrict__ dec) {
    int blk = blockIdx.x;
    int tid = threadIdx.x;

    if (blk < 40) {
        // wpack: one thread per (b, k, hw) float4
        int i = blk * 256 + tid;          // [0, 10240)
        int b = i / 5120;
        int r = i - b * 5120;
        int k = r >> 10;
        int hw = r & (HW_ - 1);
        int c0 = 2 * k, c1 = 2 * k + 1;
        const float* sb = scores + (size_t)b * 2 * C_ * HW_ + hw;
        float e00 = __expf(sb[(0 * C_ + c0) * HW_]);
        float e10 = __expf(sb[(0 * C_ + c1) * HW_]);
        float e01 = __expf(sb[(1 * C_ + c0) * HW_]);
        float e11 = __expf(sb[(1 * C_ + c1) * HW_]);
        g_pc4[((size_t)b * 8 + k) * HW_ + hw] = make_float4(e00, e10, e01, e11);
    } else if (blk < 56) {
        // p1pack: groups 5,6
        int i = (blk - 40) * 256 + tid;   // [0, 4096)
        int b = i >> 11;
        int r = i & 2047;
        int g5 = r >> 10;                 // 0 -> group5 (c 0..3), 1 -> group6 (c 4..7)
        int hw = r & (HW_ - 1);
        int cb = 4 * g5;
        const float* pb = pp + (size_t)b * 30 * HW_ + hw;
        float4 v = make_float4(pb[(3 * (cb + 0) + 1) * HW_],
                               pb[(3 * (cb + 1) + 1) * HW_],
                               pb[(3 * (cb + 2) + 1) * HW_],
                               pb[(3 * (cb + 3) + 1) * HW_]);
        g_pc4[((size_t)b * 8 + 5 + g5) * HW_ + hw] = v;
    } else if (blk < 64) {
        // p1tail: group 7 .xy = (p1[8], p1[9])
        int i = (blk - 56) * 256 + tid;   // [0, 2048)
        int b = i >> 10;
        int hw = i & (HW_ - 1);
        const float* pb = pp + (size_t)b * 30 * HW_ + hw;
        float2 v = make_float2(pb[25 * HW_], pb[28 * HW_]);
        *(float2*)&g_pc4[((size_t)b * 8 + 7) * HW_ + hw].x = v;
    } else if (blk < 104) {
        // p0pack
        int i = (blk - 64) * 256 + tid;   // [0, 10240)
        int b = i / 5120;
        int r = i - b * 5120;
        int k = r >> 10;
        int hw = r & (HW_ - 1);
        const float* pb = pp + (size_t)b * 30 * HW_ + hw;
        float2 v = make_float2(pb[(3 * (2 * k)) * HW_] * LOG2E,
                               pb[(3 * (2 * k + 1)) * HW_] * LOG2E);
        g_p0f2[((size_t)b * 5 + k) * HW_ + hw] = v;
    } else if (blk < 112) {
        // bev: one thread per (b,hw) cell
        int i = (blk - 104) * 256 + tid;  // [0, 2048)
        int b = i >> 10;
        int hw = i & (HW_ - 1);
        float x1a[2], y1a[2], x2a[2], y2a[2], area[2];
#pragma unroll
        for (int a = 0; a < 2; a++) {
            const float* d7 = dec + ((size_t)b * NBOX + hw * 2 + a) * 7;
            float x = d7[0], y = d7[1], dx = d7[3], dy = d7[4], yaw = d7[6];
            float normed = fabsf(yaw - floorf(yaw / PI_F + 0.5f) * PI_F);
            bool sw = normed > 0.25f * PI_F;
            float w = sw ? dy : dx;
            float h = sw ? dx : dy;
            x1a[a] = x - 0.5f * w; y1a[a] = y - 0.5f * h;
            x2a[a] = x + 0.5f * w; y2a[a] = y + 0.5f * h;
            area[a] = (x2a[a] - x1a[a]) * (y2a[a] - y1a[a]);
        }
        float4* bv = g_bev4 + (size_t)b * 2 * HW_ + hw;
        bv[0]   = make_float4(x1a[0], x1a[1], y1a[0], y1a[1]);
        bv[HW_] = make_float4(x2a[0], x2a[1], y2a[0], y2a[1]);
        *(float2*)&g_pc4[((size_t)b * 8 + 7) * HW_ + hw].z = make_float2(area[0], area[1]);
    } else {
        // scsum
        int s = blk - 112;
        int b = s / C_, c = s % C_;
        __shared__ float red[256];
        float acc = 0.f;
        for (int m = tid; m < NBOX; m += 256) {
            int a = m & 1, hw = m >> 1;
            acc += __expf(scores[((b * A_ + a) * C_ + c) * HW_ + hw]);
        }
        red[tid] = acc;
        __syncthreads();
#pragma unroll
        for (int o = 128; o > 0; o >>= 1) {
            if (tid < o) red[tid] += red[tid + o];
            __syncthreads();
        }
        if (tid == 0) g_scinv[b * C_ + c] = 1.0f / red[0];
    }
}

// ---------------------------------------------------------------------------
// K2 main: blocks [0,1024): block q -> n-quad q>>1, m-half q&1 (512 m-cells,
//          4 tiles). One warp per n-cell. Partials to g_part.
//          Blocks >= 1024: bbox/pp pass-through copies (overlapped).
// ---------------------------------------------------------------------------
__device__ __forceinline__ float iou1(float ax1, float ay1, float ax2, float ay2, float aa,
                                      float bx1, float by1, float bx2, float by2, float ba) {
    float ltx = fmaxf(ax1, bx1);
    float lty = fmaxf(ay1, by1);
    float rbx = fminf(ax2, bx2);
    float rby = fminf(ay2, by2);
    float w = fmaxf(rbx - ltx, 0.f);
    float h = fmaxf(rby - lty, 0.f);
    float inter = w * h;
    float uni = fmaxf(aa + ba - inter, 1e-6f);
    return inter * LOG2E * rcpf(uni);
}

__global__ void __launch_bounds__(128, 5) k_main(
        const float* __restrict__ bbox, const float* __restrict__ pp,
        float* __restrict__ out) {
    if (blockIdx.x >= 1024) {
        // pass-through copies: 88 blocks * 256 float4 = 22528 f4
        int base = (blockIdx.x - 1024) * 256 + threadIdx.x;
#pragma unroll
        for (int r = 0; r < 2; r++) {
            int i = base + r * 128;
            if (i < 7168)
                ((float4*)(out + OUT_BBOX))[i] = ((const float4*)bbox)[i];
            else
                ((float4*)(out + OUT_PP))[i - 7168] = ((const float4*)pp)[i - 7168];
        }
        return;
    }

    __shared__ __align__(16) float4     sb[2][2 * TILE];  // bev groups
    __shared__ __align__(16) ulonglong2 sp[2][8 * TILE];  // pc groups

    int tid = threadIdx.x;
    int lane = tid & 31;
    int h = blockIdx.x & 1;                      // m-half
    int gw = (blockIdx.x >> 1) * 4 + (tid >> 5); // n-cell index [0,2048)
    int b = gw >> 10;
    int hwn = gw & (HW_ - 1);

    // n-side invariants
    float4 ng0 = g_bev4[(size_t)b * 2 * HW_ + hwn];
    float4 ng1 = g_bev4[(size_t)b * 2 * HW_ + HW_ + hwn];
    float4 ng7 = g_pc4[(size_t)b * 8 * HW_ + 7 * HW_ + hwn];
    float n0x1 = ng0.x, n1x1 = ng0.y, n0y1 = ng0.z, n1y1 = ng0.w;
    float n0x2 = ng1.x, n1x2 = ng1.y, n0y2 = ng1.z, n1y2 = ng1.w;
    float an0 = ng7.z, an1 = ng7.w;

    ull p0p[5];
#pragma unroll
    for (int k = 0; k < 5; k++) {
        float2 t = g_p0f2[((size_t)b * 5 + k) * HW_ + hwn];
        p0p[k] = pk(t.x, t.y);
    }

    ull acc0p[5], acc1p[5], sm0p[5], sm1p[5];
#pragma unroll
    for (int k = 0; k < 5; k++) { acc0p[k] = 0; acc1p[k] = 0; sm0p[k] = 0; sm1p[k] = 0; }

    const float4* gb = g_bev4 + (size_t)b * 2 * HW_ + h * 512;
    const float4* gp = g_pc4 + (size_t)b * 8 * HW_ + h * 512;

    // prefetch tile 0
    {
        uint32_t sba = (uint32_t)__cvta_generic_to_shared(&sb[0][0]);
        uint32_t spa = (uint32_t)__cvta_generic_to_shared(&sp[0][0]);
#pragma unroll
        for (int g = 0; g < 2; g++)
            cpasync16(sba + (g * TILE + tid) * 16, gb + g * HW_ + tid);
#pragma unroll
        for (int g = 0; g < 8; g++)
            cpasync16(spa + (g * TILE + tid) * 16, gp + g * HW_ + tid);
        asm volatile("cp.async.commit_group;");
    }

    for (int t = 0; t < 4; t++) {
        if (t < 3) {
            int nb = (t + 1) & 1;
            uint32_t sba = (uint32_t)__cvta_generic_to_shared(&sb[nb][0]);
            uint32_t spa = (uint32_t)__cvta_generic_to_shared(&sp[nb][0]);
            int off = (t + 1) * TILE + tid;
#pragma unroll
            for (int g = 0; g < 2; g++)
                cpasync16(sba + (g * TILE + tid) * 16, gb + g * HW_ + off);
#pragma unroll
            for (int g = 0; g < 8; g++)
                cpasync16(spa + (g * TILE + tid) * 16, gp + g * HW_ + off);
            asm volatile("cp.async.commit_group;");
            asm volatile("cp.async.wait_group 1;");
        } else {
            asm volatile("cp.async.wait_group 0;");
        }
        __syncthreads();

        const float4*     SB = sb[t & 1];
        const ulonglong2* SP = sp[t & 1];
#pragma unroll 2
        for (int j = 0; j < 4; j++) {
            int m = lane + j * 32;
            float4 bg0 = SB[m];            // (x1a0,x1a1,y1a0,y1a1)
            float4 bg1 = SB[TILE + m];     // (x2a0,x2a1,y2a0,y2a1)
            float4 G7f = ((const float4*)SP)[7 * TILE + m]; // p1[8],p1[9],area0,area1

            float q00 = iou1(n0x1, n0y1, n0x2, n0y2, an0, bg0.x, bg0.z, bg1.x, bg1.z, G7f.z);
            float q01 = iou1(n0x1, n0y1, n0x2, n0y2, an0, bg0.y, bg0.w, bg1.y, bg1.w, G7f.w);
            float q10 = iou1(n1x1, n1y1, n1x2, n1y2, an1, bg0.x, bg0.z, bg1.x, bg1.z, G7f.z);
            float q11 = iou1(n1x1, n1y1, n1x2, n1y2, an1, bg0.y, bg0.w, bg1.y, bg1.w, G7f.w);

            float e00 = ex2(q00), e01 = ex2(q01);
            float e10 = ex2(q10), e11 = ex2(q11);
            ull e00s = pk(e00, e00), e01s = pk(e01, e01);
            ull e10s = pk(e10, e10), e11s = pk(e11, e11);
            ull es0s = pk(e00 + e01, e00 + e01);
            ull es1s = pk(e10 + e11, e10 + e11);

            ulonglong2 G5 = SP[5 * TILE + m];
            ulonglong2 G6 = SP[6 * TILE + m];
            ull p1p[5] = { G5.x, G5.y, G6.x, G6.y, pk(G7f.x, G7f.y) };

#pragma unroll
            for (int k = 0; k < 5; k++) {
                ull tt = mul2(p0p[k], p1p[k]);
                float b0, b1; upk(tt, b0, b1);
                ull ebp = pk(ex2(b0), ex2(b1));        // exp(bias) c-pair

                ulonglong2 Wk = SP[k * TILE + m];      // w0p = a0 pair, w1p = a1 pair
                ull s0p = fma2(e01s, Wk.y, mul2(e00s, Wk.x));
                ull s1p = fma2(e11s, Wk.y, mul2(e10s, Wk.x));
                acc0p[k] = fma2(ebp, s0p, acc0p[k]);
                acc1p[k] = fma2(ebp, s1p, acc1p[k]);
                sm0p[k]  = fma2(ebp, es0s, sm0p[k]);
                sm1p[k]  = fma2(ebp, es1s, sm1p[k]);
            }
        }
        __syncthreads();
    }

    // warp butterfly reduction
#pragma unroll
    for (int o = 16; o > 0; o >>= 1) {
#pragma unroll
        for (int k = 0; k < 5; k++) {
            acc0p[k] = add2(acc0p[k], __shfl_xor_sync(0xffffffffu, acc0p[k], o));
            acc1p[k] = add2(acc1p[k], __shfl_xor_sync(0xffffffffu, acc1p[k], o));
            sm0p[k]  = add2(sm0p[k],  __shfl_xor_sync(0xffffffffu, sm0p[k],  o));
            sm1p[k]  = add2(sm1p[k],  __shfl_xor_sync(0xffffffffu, sm1p[k],  o));
        }
    }

    if (lane == 0) {
        ull* P = g_part + ((size_t)(h * NBOX + gw) * 5) * 4;
#pragma unroll
        for (int k = 0; k < 5; k++) {
            P[k * 4 + 0] = acc0p[k];
            P[k * 4 + 1] = acc1p[k];
            P[k * 4 + 2] = sm0p[k];
            P[k * 4 + 3] = sm1p[k];
        }
    }
}

// ---------------------------------------------------------------------------
// K3 combine: add m-half partials, divide, scale, store. 2048*5 threads.
// ---------------------------------------------------------------------------
__global__ void k_comb(float* __restrict__ out) {
    int i = blockIdx.x * 256 + threadIdx.x;   // [0, 10240)
    int cell = i / 5;
    int k = i - cell * 5;
    int b = cell >> 10;
    int hwn = cell & (HW_ - 1);

    const ull* P0 = g_part + ((size_t)cell * 5 + k) * 4;
    const ull* P1 = P0 + (size_t)NBOX * 5 * 4;
    ull a0 = add2(P0[0], P1[0]);
    ull a1 = add2(P0[1], P1[1]);
    ull s0 = add2(P0[2], P1[2]);
    ull s1 = add2(P0[3], P1[3]);

    int c0 = 2 * k, c1 = 2 * k + 1;
    float i0 = g_scinv[b * C_ + c0];
    float i1 = g_scinv[b * C_ + c1];
    float v0, v1, d0, d1;
    upk(a0, v0, v1); upk(s0, d0, d1);
    out[((b * A_ + 0) * C_ + c0) * HW_ + hwn] = v0 * rcpf(d0) * i0;
    out[((b * A_ + 0) * C_ + c1) * HW_ + hwn] = v1 * rcpf(d1) * i1;
    upk(a1, v0, v1); upk(s1, d0, d1);
    out[((b * A_ + 1) * C_ + c0) * HW_ + hwn] = v0 * rcpf(d0) * i0;
    out[((b * A_ + 1) * C_ + c1) * HW_ + hwn] = v1 * rcpf(d1) * i1;
}

extern "C" void kernel_launch(void* const* d_in, const int* in_sizes, int n_in,
                              void* d_out, int out_size) {
    const float* scores = (const float*)d_in[0];
    const float* bbox = (const float*)d_in[1];
    const float* pp = (const float*)d_in[2];
    const float* dec = (const float*)d_in[3];
    float* out = (float*)d_out;

    k_fused<<<132, 256>>>(scores, pp, dec);
    k_main<<<1024 + 88, 128>>>(bbox, pp, out);
    k_comb<<<40, 256>>>(out);
}

// round 11
// speedup vs baseline: 1.0244x; 1.0200x over previous
#include <cuda_runtime.h>
#include <cstdint>

// Problem constants
#define BATCH 2
#define A_    2
#define C_    10
#define HW_   1024
#define NBOX  2048
#define TILE  128
#define LOG2E 1.4426950408889634f
#define PI_F  3.14159265358979323846f

// Output layout: out_scores [0,40960) | bbox [40960,69632) | pp [69632,131072)
#define OUT_BBOX 40960
#define OUT_PP   69632

// ---------------- scratch tables (SoA-group layouts) ----------------
// g_bev4: [b][2][HW] float4
//   g0 = (x1a0, x1a1, y1a0, y1a1)   g1 = (x2a0, x2a1, y2a0, y2a1)
__device__ __align__(16) float4 g_bev4[BATCH * 2 * HW_];
// g_pc4: [b][8][HW] float4
//   g=0..4 : (w[2k,a0], w[2k+1,a0], w[2k,a1], w[2k+1,a1])   (w = exp(score))
//   g=5    : (p1[0..3])   g=6 : (p1[4..7])   g=7 : (p1[8],p1[9],area0,area1)
__device__ __align__(16) float4 g_pc4[BATCH * 8 * HW_];
// g_p0f2: [b][k][hw] float2   (p0[2k],p0[2k+1]) * log2e
__device__ __align__(8)  float2 g_p0f2[BATCH * 5 * HW_];
__device__ float g_scinv[BATCH * C_];

typedef unsigned long long ull;
// partial sums: [h][cell][k][{acc0,acc1,sm0,sm1}]
__device__ __align__(16) ull g_part[2 * NBOX * 5 * 4];

// ---------------- helpers ----------------
__device__ __forceinline__ float ex2(float x) {
    float y; asm("ex2.approx.f32 %0, %1;" : "=f"(y) : "f"(x)); return y;
}
__device__ __forceinline__ float rcpf(float x) {
    float y; asm("rcp.approx.f32 %0, %1;" : "=f"(y) : "f"(x)); return y;
}
__device__ __forceinline__ ull pk(float a, float b) {
    ull r; asm("mov.b64 %0, {%1,%2};" : "=l"(r) : "f"(a), "f"(b)); return r;
}
__device__ __forceinline__ void upk(ull v, float& a, float& b) {
    asm("mov.b64 {%0,%1}, %2;" : "=f"(a), "=f"(b) : "l"(v));
}
__device__ __forceinline__ ull mul2(ull a, ull b) {
    ull r; asm("mul.rn.f32x2 %0, %1, %2;" : "=l"(r) : "l"(a), "l"(b)); return r;
}
__device__ __forceinline__ ull fma2(ull a, ull b, ull c) {
    ull r; asm("fma.rn.f32x2 %0, %1, %2, %3;" : "=l"(r) : "l"(a), "l"(b), "l"(c)); return r;
}
__device__ __forceinline__ ull add2(ull a, ull b) {
    ull r; asm("add.rn.f32x2 %0, %1, %2;" : "=l"(r) : "l"(a), "l"(b)); return r;
}
__device__ __forceinline__ void cpasync16(uint32_t saddr, const void* g) {
    asm volatile("cp.async.cg.shared.global [%0], [%1], 16;" :: "r"(saddr), "l"(g));
}

// ---------------------------------------------------------------------------
// K1 prep: wide, coalesced, elementwise slices ONLY (scsum moved to k_main).
//   [0,40)    wpack : exp(scores) -> g_pc4 groups 0..4
//   [40,56)   p1pack: pp -> g_pc4 groups 5,6
//   [56,64)   p1tail: pp -> g_pc4 group 7 .xy
//   [64,104)  p0pack: pp*log2e -> g_p0f2
//   [104,112) bev   : dec -> g_bev4 + areas -> g_pc4 group 7 .zw
// ---------------------------------------------------------------------------
__global__ void k_fused(const float* __restrict__ scores,
                        const float* __restrict__ pp,
                        const float* __restrict__ dec) {
    int blk = blockIdx.x;
    int tid = threadIdx.x;

    if (blk < 40) {
        // wpack: one thread per (b, k, hw) float4
        int i = blk * 256 + tid;          // [0, 10240)
        int b = i / 5120;
        int r = i - b * 5120;
        int k = r >> 10;
        int hw = r & (HW_ - 1);
        int c0 = 2 * k, c1 = 2 * k + 1;
        const float* sb = scores + (size_t)b * 2 * C_ * HW_ + hw;
        float e00 = __expf(sb[(0 * C_ + c0) * HW_]);
        float e10 = __expf(sb[(0 * C_ + c1) * HW_]);
        float e01 = __expf(sb[(1 * C_ + c0) * HW_]);
        float e11 = __expf(sb[(1 * C_ + c1) * HW_]);
        g_pc4[((size_t)b * 8 + k) * HW_ + hw] = make_float4(e00, e10, e01, e11);
    } else if (blk < 56) {
        // p1pack: groups 5,6
        int i = (blk - 40) * 256 + tid;   // [0, 4096)
        int b = i >> 11;
        int r = i & 2047;
        int g5 = r >> 10;                 // 0 -> group5 (c 0..3), 1 -> group6 (c 4..7)
        int hw = r & (HW_ - 1);
        int cb = 4 * g5;
        const float* pb = pp + (size_t)b * 30 * HW_ + hw;
        float4 v = make_float4(pb[(3 * (cb + 0) + 1) * HW_],
                               pb[(3 * (cb + 1) + 1) * HW_],
                               pb[(3 * (cb + 2) + 1) * HW_],
                               pb[(3 * (cb + 3) + 1) * HW_]);
        g_pc4[((size_t)b * 8 + 5 + g5) * HW_ + hw] = v;
    } else if (blk < 64) {
        // p1tail: group 7 .xy = (p1[8], p1[9])
        int i = (blk - 56) * 256 + tid;   // [0, 2048)
        int b = i >> 10;
        int hw = i & (HW_ - 1);
        const float* pb = pp + (size_t)b * 30 * HW_ + hw;
        float2 v = make_float2(pb[25 * HW_], pb[28 * HW_]);
        *(float2*)&g_pc4[((size_t)b * 8 + 7) * HW_ + hw].x = v;
    } else if (blk < 104) {
        // p0pack
        int i = (blk - 64) * 256 + tid;   // [0, 10240)
        int b = i / 5120;
        int r = i - b * 5120;
        int k = r >> 10;
        int hw = r & (HW_ - 1);
        const float* pb = pp + (size_t)b * 30 * HW_ + hw;
        float2 v = make_float2(pb[(3 * (2 * k)) * HW_] * LOG2E,
                               pb[(3 * (2 * k + 1)) * HW_] * LOG2E);
        g_p0f2[((size_t)b * 5 + k) * HW_ + hw] = v;
    } else {
        // bev: one thread per (b,hw) cell
        int i = (blk - 104) * 256 + tid;  // [0, 2048)
        int b = i >> 10;
        int hw = i & (HW_ - 1);
        float x1a[2], y1a[2], x2a[2], y2a[2], area[2];
#pragma unroll
        for (int a = 0; a < 2; a++) {
            const float* d7 = dec + ((size_t)b * NBOX + hw * 2 + a) * 7;
            float x = d7[0], y = d7[1], dx = d7[3], dy = d7[4], yaw = d7[6];
            float normed = fabsf(yaw - floorf(yaw / PI_F + 0.5f) * PI_F);
            bool sw = normed > 0.25f * PI_F;
            float w = sw ? dy : dx;
            float h = sw ? dx : dy;
            x1a[a] = x - 0.5f * w; y1a[a] = y - 0.5f * h;
            x2a[a] = x + 0.5f * w; y2a[a] = y + 0.5f * h;
            area[a] = (x2a[a] - x1a[a]) * (y2a[a] - y1a[a]);
        }
        float4* bv = g_bev4 + (size_t)b * 2 * HW_ + hw;
        bv[0]   = make_float4(x1a[0], x1a[1], y1a[0], y1a[1]);
        bv[HW_] = make_float4(x2a[0], x2a[1], y2a[0], y2a[1]);
        *(float2*)&g_pc4[((size_t)b * 8 + 7) * HW_ + hw].z = make_float2(area[0], area[1]);
    }
}

// ---------------------------------------------------------------------------
// K2 main: blocks [0,1024): compute (n-quad, m-half). One warp per n-cell.
//          blocks [1024,1112): bbox/pp pass-through copies (overlapped).
//          blocks [1112,1132): score-softmax denominators (overlapped;
//                              g_scinv consumed only by k_comb).
// ---------------------------------------------------------------------------
__device__ __forceinline__ float iou1(float ax1, float ay1, float ax2, float ay2, float aa,
                                      float bx1, float by1, float bx2, float by2, float ba) {
    float ltx = fmaxf(ax1, bx1);
    float lty = fmaxf(ay1, by1);
    float rbx = fminf(ax2, bx2);
    float rby = fminf(ay2, by2);
    float w = fmaxf(rbx - ltx, 0.f);
    float h = fmaxf(rby - lty, 0.f);
    float inter = w * h;
    float uni = fmaxf(aa + ba - inter, 1e-6f);
    return inter * LOG2E * rcpf(uni);
}

__global__ void __launch_bounds__(128, 5) k_main(
        const float* __restrict__ scores,
        const float* __restrict__ bbox, const float* __restrict__ pp,
        float* __restrict__ out) {
    if (blockIdx.x >= 1112) {
        // scsum: one (b,c) per block, 128 threads
        int s = blockIdx.x - 1112;
        int b = s / C_, c = s % C_;
        int tid = threadIdx.x;
        __shared__ float red[128];
        float acc = 0.f;
        for (int m = tid; m < NBOX; m += 128) {
            int a = m & 1, hw = m >> 1;
            acc += __expf(scores[((b * A_ + a) * C_ + c) * HW_ + hw]);
        }
        red[tid] = acc;
        __syncthreads();
#pragma unroll
        for (int o = 64; o > 0; o >>= 1) {
            if (tid < o) red[tid] += red[tid + o];
            __syncthreads();
        }
        if (tid == 0) g_scinv[b * C_ + c] = 1.0f / red[0];
        return;
    }
    if (blockIdx.x >= 1024) {
        // pass-through copies: 88 blocks * 256 float4 = 22528 f4
        int base = (blockIdx.x - 1024) * 256 + threadIdx.x;
#pragma unroll
        for (int r = 0; r < 2; r++) {
            int i = base + r * 128;
            if (i < 7168)
                ((float4*)(out + OUT_BBOX))[i] = ((const float4*)bbox)[i];
            else
                ((float4*)(out + OUT_PP))[i - 7168] = ((const float4*)pp)[i - 7168];
        }
        return;
    }

    __shared__ __align__(16) float4     sb[2][2 * TILE];  // bev groups
    __shared__ __align__(16) ulonglong2 sp[2][8 * TILE];  // pc groups

    int tid = threadIdx.x;
    int lane = tid & 31;
    int h = blockIdx.x & 1;                      // m-half
    int gw = (blockIdx.x >> 1) * 4 + (tid >> 5); // n-cell index [0,2048)
    int b = gw >> 10;
    int hwn = gw & (HW_ - 1);

    // n-side invariants
    float4 ng0 = g_bev4[(size_t)b * 2 * HW_ + hwn];
    float4 ng1 = g_bev4[(size_t)b * 2 * HW_ + HW_ + hwn];
    float4 ng7 = g_pc4[(size_t)b * 8 * HW_ + 7 * HW_ + hwn];
    float n0x1 = ng0.x, n1x1 = ng0.y, n0y1 = ng0.z, n1y1 = ng0.w;
    float n0x2 = ng1.x, n1x2 = ng1.y, n0y2 = ng1.z, n1y2 = ng1.w;
    float an0 = ng7.z, an1 = ng7.w;

    ull p0p[5];
#pragma unroll
    for (int k = 0; k < 5; k++) {
        float2 t = g_p0f2[((size_t)b * 5 + k) * HW_ + hwn];
        p0p[k] = pk(t.x, t.y);
    }

    ull acc0p[5], acc1p[5], sm0p[5], sm1p[5];
#pragma unroll
    for (int k = 0; k < 5; k++) { acc0p[k] = 0; acc1p[k] = 0; sm0p[k] = 0; sm1p[k] = 0; }

    const float4* gb = g_bev4 + (size_t)b * 2 * HW_ + h * 512;
    const float4* gp = g_pc4 + (size_t)b * 8 * HW_ + h * 512;

    // prefetch tile 0
    {
        uint32_t sba = (uint32_t)__cvta_generic_to_shared(&sb[0][0]);
        uint32_t spa = (uint32_t)__cvta_generic_to_shared(&sp[0][0]);
#pragma unroll
        for (int g = 0; g < 2; g++)
            cpasync16(sba + (g * TILE + tid) * 16, gb + g * HW_ + tid);
#pragma unroll
        for (int g = 0; g < 8; g++)
            cpasync16(spa + (g * TILE + tid) * 16, gp + g * HW_ + tid);
        asm volatile("cp.async.commit_group;");
    }

    for (int t = 0; t < 4; t++) {
        if (t < 3) {
            int nb = (t + 1) & 1;
            uint32_t sba = (uint32_t)__cvta_generic_to_shared(&sb[nb][0]);
            uint32_t spa = (uint32_t)__cvta_generic_to_shared(&sp[nb][0]);
            int off = (t + 1) * TILE + tid;
#pragma unroll
            for (int g = 0; g < 2; g++)
                cpasync16(sba + (g * TILE + tid) * 16, gb + g * HW_ + off);
#pragma unroll
            for (int g = 0; g < 8; g++)
                cpasync16(spa + (g * TILE + tid) * 16, gp + g * HW_ + off);
            asm volatile("cp.async.commit_group;");
            asm volatile("cp.async.wait_group 1;");
        } else {
            asm volatile("cp.async.wait_group 0;");
        }
        __syncthreads();

        const float4*     SB = sb[t & 1];
        const ulonglong2* SP = sp[t & 1];
#pragma unroll 2
        for (int j = 0; j < 4; j++) {
            int m = lane + j * 32;
            float4 bg0 = SB[m];            // (x1a0,x1a1,y1a0,y1a1)
            float4 bg1 = SB[TILE + m];     // (x2a0,x2a1,y2a0,y2a1)
            float4 G7f = ((const float4*)SP)[7 * TILE + m]; // p1[8],p1[9],area0,area1

            float q00 = iou1(n0x1, n0y1, n0x2, n0y2, an0, bg0.x, bg0.z, bg1.x, bg1.z, G7f.z);
            float q01 = iou1(n0x1, n0y1, n0x2, n0y2, an0, bg0.y, bg0.w, bg1.y, bg1.w, G7f.w);
            float q10 = iou1(n1x1, n1y1, n1x2, n1y2, an1, bg0.x, bg0.z, bg1.x, bg1.z, G7f.z);
            float q11 = iou1(n1x1, n1y1, n1x2, n1y2, an1, bg0.y, bg0.w, bg1.y, bg1.w, G7f.w);

            float e00 = ex2(q00), e01 = ex2(q01);
            float e10 = ex2(q10), e11 = ex2(q11);
            ull e00s = pk(e00, e00), e01s = pk(e01, e01);
            ull e10s = pk(e10, e10), e11s = pk(e11, e11);
            ull es0s = pk(e00 + e01, e00 + e01);
            ull es1s = pk(e10 + e11, e10 + e11);

            ulonglong2 G5 = SP[5 * TILE + m];
            ulonglong2 G6 = SP[6 * TILE + m];
            ull p1p[5] = { G5.x, G5.y, G6.x, G6.y, pk(G7f.x, G7f.y) };

#pragma unroll
            for (int k = 0; k < 5; k++) {
                ull tt = mul2(p0p[k], p1p[k]);
                float b0, b1; upk(tt, b0, b1);
                ull ebp = pk(ex2(b0), ex2(b1));        // exp(bias) c-pair

                ulonglong2 Wk = SP[k * TILE + m];      // w0p = a0 pair, w1p = a1 pair
                ull s0p = fma2(e01s, Wk.y, mul2(e00s, Wk.x));
                ull s1p = fma2(e11s, Wk.y, mul2(e10s, Wk.x));
                acc0p[k] = fma2(ebp, s0p, acc0p[k]);
                acc1p[k] = fma2(ebp, s1p, acc1p[k]);
                sm0p[k]  = fma2(ebp, es0s, sm0p[k]);
                sm1p[k]  = fma2(ebp, es1s, sm1p[k]);
            }
        }
        __syncthreads();
    }

    // warp butterfly reduction
#pragma unroll
    for (int o = 16; o > 0; o >>= 1) {
#pragma unroll
        for (int k = 0; k < 5; k++) {
            acc0p[k] = add2(acc0p[k], __shfl_xor_sync(0xffffffffu, acc0p[k], o));
            acc1p[k] = add2(acc1p[k], __shfl_xor_sync(0xffffffffu, acc1p[k], o));
            sm0p[k]  = add2(sm0p[k],  __shfl_xor_sync(0xffffffffu, sm0p[k],  o));
            sm1p[k]  = add2(sm1p[k],  __shfl_xor_sync(0xffffffffu, sm1p[k],  o));
        }
    }

    if (lane == 0) {
        ull* P = g_part + ((size_t)(h * NBOX + gw) * 5) * 4;
#pragma unroll
        for (int k = 0; k < 5; k++) {
            P[k * 4 + 0] = acc0p[k];
            P[k * 4 + 1] = acc1p[k];
            P[k * 4 + 2] = sm0p[k];
            P[k * 4 + 3] = sm1p[k];
        }
    }
}

// ---------------------------------------------------------------------------
// K3 combine: add m-half partials, divide, scale, store. 2048*5 threads.
// ---------------------------------------------------------------------------
__global__ void k_comb(float* __restrict__ out) {
    int i = blockIdx.x * 256 + threadIdx.x;   // [0, 10240)
    int cell = i / 5;
    int k = i - cell * 5;
    int b = cell >> 10;
    int hwn = cell & (HW_ - 1);

    const ull* P0 = g_part + ((size_t)cell * 5 + k) * 4;
    const ull* P1 = P0 + (size_t)NBOX * 5 * 4;
    ull a0 = add2(P0[0], P1[0]);
    ull a1 = add2(P0[1], P1[1]);
    ull s0 = add2(P0[2], P1[2]);
    ull s1 = add2(P0[3], P1[3]);

    int c0 = 2 * k, c1 = 2 * k + 1;
    float i0 = g_scinv[b * C_ + c0];
    float i1 = g_scinv[b * C_ + c1];
    float v0, v1, d0, d1;
    upk(a0, v0, v1); upk(s0, d0, d1);
    out[((b * A_ + 0) * C_ + c0) * HW_ + hwn] = v0 * rcpf(d0) * i0;
    out[((b * A_ + 0) * C_ + c1) * HW_ + hwn] = v1 * rcpf(d1) * i1;
    upk(a1, v0, v1); upk(s1, d0, d1);
    out[((b * A_ + 1) * C_ + c0) * HW_ + hwn] = v0 * rcpf(d0) * i0;
    out[((b * A_ + 1) * C_ + c1) * HW_ + hwn] = v1 * rcpf(d1) * i1;
}

extern "C" void kernel_launch(void* const* d_in, const int* in_sizes, int n_in,
                              void* d_out, int out_size) {
    const float* scores = (const float*)d_in[0];
    const float* bbox = (const float*)d_in[1];
    const float* pp = (const float*)d_in[2];
    const float* dec = (const float*)d_in[3];
    float* out = (float*)d_out;

    k_fused<<<112, 256>>>(scores, pp, dec);
    k_main<<<1024 + 88 + 20, 128>>>(scores, bbox, pp, out);
    k_comb<<<40, 256>>>(out);
}